// round 15
// baseline (speedup 1.0000x reference)
#include <cuda_runtime.h>

#define NH 8
#define DD 1024
#define MM 2048
#define PIX4 12288           // 128*128*3 / 4
#define MSLICE 128           // m per wsum tile
#define XTW 128              // float4 columns per wsum tile
#define XT (PIX4/XTW)        // 96
#define NTILES (XT*(MM/MSLICE))   // 96*16 = 1536
#define WGRID 608            // wsum grid: 152 SMs x 4

#define STAGES 4
#define SROWS 4                          // m-rows per stage
#define ROWB (XTW*16)                    // 2048 bytes per row
#define STAGE_BYTES (SROWS*ROWB)         // 8192
#define NSTG (MSLICE/SROWS)              // 32 stages per tile
// dynamic smem layout (wsum)
#define SM_W2S   (STAGES*STAGE_BYTES)    // 32768
#define SM_MBAR  (SM_W2S + MSLICE*NH*8)  // 40960
#define SM_TILE  (SM_MBAR + STAGES*8)    // 40992
#define SM_TOTAL (SM_TILE + 16)          // 41008

// Replay lifecycle (4 sequential launches, no grid barriers):
//   proj_q : zeroes g_t/g_c/g_sums, writes g_q
//   proj_t : REDG-accumulates g_t, atomic-accumulates g_c
//   logits : reads g_t/g_c/K -> writes g_wt, accumulates g_sums,
//            zeroes d_out, resets g_ctr
//   wsum   : consumes g_wt/g_sums/g_ctr
__device__ float g_q[NH*DD];
__device__ float g_t[NH*DD];
__device__ float g_c[NH];
__device__ float g_sums[NH];
__device__ float g_wt[MM*NH];
__device__ int   g_ctr;

__device__ __forceinline__ unsigned long long pk2(float a, float b){
    unsigned long long r;
    asm("mov.b64 %0, {%1, %2};" : "=l"(r) : "f"(a), "f"(b));
    return r;
}
__device__ __forceinline__ void fma2(unsigned long long &acc, unsigned long long v, unsigned long long w){
    asm("fma.rn.f32x2 %0, %1, %2, %0;" : "+l"(acc) : "l"(v), "l"(w));
}
__device__ __forceinline__ void upk2(unsigned long long p, float &a, float &b){
    asm("mov.b64 {%0, %1}, %2;" : "=f"(a), "=f"(b) : "l"(p));
}
__device__ __forceinline__ unsigned int smem_u32(const void* p){
    unsigned int a;
    asm("{ .reg .u64 t; cvta.to.shared.u64 t, %1; cvt.u32.u64 %0, t; }" : "=r"(a) : "l"(p));
    return a;
}
__device__ __forceinline__ void mbar_wait(unsigned int mbar, unsigned int phase){
    asm volatile(
        "{\n\t.reg .pred P;\n"
        "LW%=:\n\t"
        "mbarrier.try_wait.parity.acquire.cta.shared::cta.b64 P, [%0], %1, 0x989680;\n\t"
        "@P bra LD%=;\n\t"
        "bra LW%=;\n"
        "LD%=:\n\t}"
        :: "r"(mbar), "r"(phase) : "memory");
}
__device__ __forceinline__ void issue_stage(unsigned int dst, const float4* src, unsigned int mbar){
    asm volatile("mbarrier.arrive.expect_tx.shared.b64 _, [%0], %1;"
                 :: "r"(mbar), "r"((unsigned)STAGE_BYTES) : "memory");
    #pragma unroll
    for (int r = 0; r < SROWS; r++){
        asm volatile("cp.async.bulk.shared::cluster.global.mbarrier::complete_tx::bytes [%0], [%1], %2, [%3];"
            :: "r"(dst + r*ROWB), "l"(src + (size_t)r*PIX4), "r"((unsigned)ROWB), "r"(mbar)
            : "memory");
    }
}

// ---------------------------------------------------------------------------
// Kernel A (R5-proven): q[h,e] = Q . WQ[h,e,:] + bQ[h,e]   (warp per (h,e))
//           also zeroes g_t / g_c / g_sums for this graph replay
// ---------------------------------------------------------------------------
__global__ void proj_q_kernel(const float* __restrict__ Q,
                              const float* __restrict__ WQ,
                              const float* __restrict__ bQ) {
    int tid = threadIdx.x;
    int gid = (blockIdx.y * gridDim.x + blockIdx.x) * blockDim.x + tid;
    if (gid < NH*DD) g_t[gid] = 0.f;
    if (gid < NH) { g_c[gid] = 0.f; g_sums[gid] = 0.f; }

    int h = blockIdx.y;
    int e = blockIdx.x * 8 + (tid >> 5);
    int lane = tid & 31;
    const float4* W4 = (const float4*)WQ + (size_t)h*(DD*DD/4) + (size_t)e*(DD/4);
    const float4* Q4 = (const float4*)Q;
    float acc = 0.f;
    #pragma unroll
    for (int i = 0; i < 8; i++) {
        float4 w = __ldcs(&W4[lane + i*32]);
        float4 q = Q4[lane + i*32];
        acc += w.x*q.x + w.y*q.y + w.z*q.z + w.w*q.w;
    }
    #pragma unroll
    for (int o = 16; o; o >>= 1) acc += __shfl_xor_sync(0xffffffffu, acc, o);
    if (lane == 0) g_q[h*DD + e] = acc + bQ[h*DD + e];
}

// ---------------------------------------------------------------------------
// Kernel B: t[h,d] += sum_{e in 32-chunk} q[h,e] * WK[h,e,d]
//   float4 along d (thread tid -> d = 4*tid..+3); 256 blocks x 128 KB;
//   REDG.v4 into g_t; bias-dot partial c[h] folded in (warp 0).
// ---------------------------------------------------------------------------
#define ESL 32
__global__ void __launch_bounds__(256) proj_t_kernel(const float* __restrict__ WK,
                                                     const float* __restrict__ bK) {
    int tid = threadIdx.x;
    int h  = blockIdx.y;
    int e0 = blockIdx.x * ESL;
    const float4* Wp = (const float4*)(WK + (size_t)h*DD*DD + (size_t)e0*DD) + tid;
    const float* qp = g_q + h*DD + e0;

    float4 acc = make_float4(0.f, 0.f, 0.f, 0.f);
    #pragma unroll 8
    for (int e = 0; e < ESL; e++) {
        float qe = __ldcg(&qp[e]);
        float4 w = __ldcs(&Wp[(size_t)e*(DD/4)]);
        acc.x = fmaf(qe, w.x, acc.x);
        acc.y = fmaf(qe, w.y, acc.y);
        acc.z = fmaf(qe, w.z, acc.z);
        acc.w = fmaf(qe, w.w, acc.w);
    }
    float* p = &g_t[h*DD + tid*4];
    asm volatile("red.global.add.v4.f32 [%0], {%1, %2, %3, %4};"
                 :: "l"(p), "f"(acc.x), "f"(acc.y), "f"(acc.z), "f"(acc.w) : "memory");

    if (tid < 32) {   // c[h] partial over this e-chunk
        float v = __ldcg(&qp[tid]) * bK[h*DD + e0 + tid];
        #pragma unroll
        for (int o = 16; o; o >>= 1) v += __shfl_xor_sync(0xffffffffu, v, o);
        if (tid == 0) atomicAdd(&g_c[h], v);
    }
}

// ---------------------------------------------------------------------------
// Kernel C (R5-proven): fused logits + exp (unnormalized softmax) + sums.
//   g_wt[m][h] = exp((K[m].t[h] + c[h]) / 1024)   (no max-sub: |l| small)
//   Zero-inits d_out and resets the wsum ticket counter.
// ---------------------------------------------------------------------------
__global__ void logits_kernel(const float* __restrict__ K,
                              float4* __restrict__ out4) {
    __shared__ float4 ts4[NH*DD/4];   // 32 KB
    __shared__ float ws[8][NH];
    int tid = threadIdx.x;
    if (blockIdx.x == 0 && tid == 0) g_ctr = 0;
    for (int i = tid; i < NH*DD/4; i += 256) {
        const float* s = &g_t[i*4];
        ts4[i] = make_float4(__ldcg(s), __ldcg(s+1), __ldcg(s+2), __ldcg(s+3));
    }

    for (int idx = blockIdx.x * 256 + tid; idx < NH*PIX4; idx += 256*256)
        out4[idx] = make_float4(0.f, 0.f, 0.f, 0.f);
    __syncthreads();

    int wid = tid >> 5;
    int m = blockIdx.x * 8 + wid;
    int lane = tid & 31;
    const float4* K4 = (const float4*)K + (size_t)m*(DD/4);
    float acc[NH];
    #pragma unroll
    for (int h = 0; h < NH; h++) acc[h] = 0.f;
    #pragma unroll
    for (int i = 0; i < 8; i++) {
        float4 k4 = K4[lane + i*32];
        #pragma unroll
        for (int h = 0; h < NH; h++) {
            float4 t4 = ts4[h*256 + lane + i*32];
            acc[h] += k4.x*t4.x + k4.y*t4.y + k4.z*t4.z + k4.w*t4.w;
        }
    }
    #pragma unroll
    for (int h = 0; h < NH; h++) {
        #pragma unroll
        for (int o = 16; o; o >>= 1) acc[h] += __shfl_xor_sync(0xffffffffu, acc[h], o);
    }
    if (lane == 0) {
        #pragma unroll
        for (int h = 0; h < NH; h++) {
            float w = expf((acc[h] + __ldcg(&g_c[h])) * (1.0f/1024.0f));
            g_wt[m*NH + h] = w;
            ws[wid][h] = w;
        }
    }
    __syncthreads();
    if (tid < NH) {
        float s = 0.f;
        #pragma unroll
        for (int w8 = 0; w8 < 8; w8++) s += ws[w8][tid];
        atomicAdd(&g_sums[tid], s);
    }
}

// ---------------------------------------------------------------------------
// wsum (R14-proven 70.5us core, byte-identical): persistent tickets; 256KB
// tiles; cp.async.bulk 4-stage smem ring; 2 head-grps x 128 cols; f32x2 FMA;
// REDG.v4 output.
// ---------------------------------------------------------------------------
__global__ void __launch_bounds__(256, 4) wsum_kernel(const float* __restrict__ V,
                                                      float4* __restrict__ out4) {
    extern __shared__ char smem[];
    unsigned int sb = smem_u32(smem);
    int tid = threadIdx.x;
    int grp = tid >> 7;          // head group: heads [4g, 4g+4)
    int cid = tid & 127;         // float4 column within tile

    if (tid == 0) {
        #pragma unroll
        for (int i = 0; i < STAGES; i++)
            asm volatile("mbarrier.init.shared.b64 [%0], 1;" :: "r"(sb + SM_MBAR + i*8) : "memory");
        asm volatile("fence.proxy.async.shared::cta;" ::: "memory");
    }
    __syncthreads();

    float inv[NH];
    #pragma unroll
    for (int h = 0; h < NH; h++) inv[h] = __fdividef(1.0f, g_sums[h]);

    unsigned long long* w2s = (unsigned long long*)(smem + SM_W2S);
    int* s_tile = (int*)(smem + SM_TILE);
    int sc = 0;   // absolute stage counter -> slot/parity

    for (;;) {
        if (tid == 0) *s_tile = atomicAdd(&g_ctr, 1);
        __syncthreads();
        int t = *s_tile;
        if (t >= NTILES) break;
        int s  = t / XT;
        int xb = t - s*XT;
        int m0 = s * MSLICE;

        const float4* src = (const float4*)V + (size_t)m0*PIX4 + xb*XTW;
        if (tid == 0) {
            #pragma unroll
            for (int j = 0; j < STAGES; j++)
                issue_stage(sb + ((sc + j) & (STAGES-1))*STAGE_BYTES,
                            src + (size_t)j*SROWS*PIX4,
                            sb + SM_MBAR + ((sc + j) & (STAGES-1))*8);
        }

        for (int i = tid; i < MSLICE*NH; i += 256) {
            float w = g_wt[m0*NH + i] * inv[i & 7];
            w2s[i] = pk2(w, w);
        }
        __syncthreads();

        unsigned long long a0[4], a1[4];
        #pragma unroll
        for (int i = 0; i < 4; i++) { a0[i] = 0ull; a1[i] = 0ull; }

        #pragma unroll 1
        for (int j = 0; j < NSTG; j++) {
            int slot = (sc + j) & (STAGES-1);
            unsigned int ph = ((unsigned)(sc + j) >> 2) & 1;
            mbar_wait(sb + SM_MBAR + slot*8, ph);
            const float4* vstage = (const float4*)(smem + slot*STAGE_BYTES);
            #pragma unroll
            for (int r = 0; r < SROWS; r++) {
                float4 v = vstage[r*XTW + cid];
                unsigned long long v01 = pk2(v.x, v.y);
                unsigned long long v23 = pk2(v.z, v.w);
                const ulonglong2* wr = (const ulonglong2*)&w2s[(j*SROWS + r)*NH + grp*4];
                ulonglong2 wA = wr[0], wB = wr[1];
                fma2(a0[0], v01, wA.x); fma2(a1[0], v23, wA.x);
                fma2(a0[1], v01, wA.y); fma2(a1[1], v23, wA.y);
                fma2(a0[2], v01, wB.x); fma2(a1[2], v23, wB.x);
                fma2(a0[3], v01, wB.y); fma2(a1[3], v23, wB.y);
            }
            __syncthreads();   // slot fully consumed -> safe to refill
            if (tid == 0 && j + STAGES < NSTG)
                issue_stage(sb + ((sc + j + STAGES) & (STAGES-1))*STAGE_BYTES,
                            src + (size_t)(j + STAGES)*SROWS*PIX4,
                            sb + SM_MBAR + ((sc + j + STAGES) & (STAGES-1))*8);
        }
        sc += NSTG;

        int jj = xb*XTW + cid;
        #pragma unroll
        for (int i = 0; i < 4; i++) {
            int h = grp*4 + i;
            float x, y, z, w;
            upk2(a0[i], x, y);
            upk2(a1[i], z, w);
            float* p = (float*)&out4[h*PIX4 + jj];
            asm volatile("red.global.add.v4.f32 [%0], {%1, %2, %3, %4};"
                         :: "l"(p), "f"(x), "f"(y), "f"(z), "f"(w) : "memory");
        }
    }
}

extern "C" void kernel_launch(void* const* d_in, const int* in_sizes, int n_in,
                              void* d_out, int out_size) {
    const float* Q  = (const float*)d_in[0];
    const float* K  = (const float*)d_in[1];
    const float* V  = (const float*)d_in[2];
    const float* WQ = (const float*)d_in[3];
    const float* bQ = (const float*)d_in[4];
    const float* WK = (const float*)d_in[5];
    const float* bK = (const float*)d_in[6];

    proj_q_kernel<<<dim3(128, 8), 256>>>(Q, WQ, bQ);
    proj_t_kernel<<<dim3(DD/ESL, 8), 256>>>(WK, bK);
    logits_kernel<<<256, 256>>>(K, (float4*)d_out);
    wsum_kernel<<<WGRID, 256, SM_TOTAL>>>(V, (float4*)d_out);
}

// round 16
// speedup vs baseline: 1.0009x; 1.0009x over previous
#include <cuda_runtime.h>

#define NH 8
#define DD 1024
#define MM 2048
#define PIX4 12288           // 128*128*3 / 4
#define MSLICE 128           // m per wsum tile
#define XTW 128              // float4 columns per wsum tile
#define XT (PIX4/XTW)        // 96
#define NTILES (XT*(MM/MSLICE))   // 96*16 = 1536
#define PGRID 512            // prep: 2 tasks/block exactly
#define WGRID 608            // wsum: 152 SMs x 4
#define NPROD 256            // wsum producer blocks (logits)

#define STAGES 4
#define SROWS 4                          // m-rows per stage
#define ROWB (XTW*16)                    // 2048 bytes per row
#define STAGE_BYTES (SROWS*ROWB)         // 8192
#define NSTG (MSLICE/SROWS)              // 32 stages per tile
// dynamic smem layout (wsum): [0,32768) stage ring / ts4 (phase-exclusive)
#define SM_W2S   (STAGES*STAGE_BYTES)    // 32768  (w2s; ws aliases it in logits)
#define SM_MBAR  (SM_W2S + MSLICE*NH*8)  // 40960
#define SM_TILE  (SM_MBAR + STAGES*8)    // 40992
#define SM_TOTAL (SM_TILE + 16)          // 41008

// Replay lifecycle (2 launches):
//   prep : resets g_ctr/g_wready, zeroes g_sums; accumulates g_t (REDG) + g_c
//          (g_t/g_c were zeroed by the PREVIOUS wsum; module-load zeroes run 1)
//   wsum : producers (bx<256) read g_t/g_c/K -> g_wt/g_sums, zero d_out,
//          arrive g_wready; everyone streams V; block 0 zeroes g_t/g_c at end.
__device__ float g_q_unused;   // (q lives in smem only)
__device__ float g_t[NH*DD];
__device__ float g_c[NH];
__device__ float g_sums[NH];
__device__ float g_wt[MM*NH];
__device__ int   g_ctr;
__device__ int   g_wready;

__device__ __forceinline__ unsigned long long pk2(float a, float b){
    unsigned long long r;
    asm("mov.b64 %0, {%1, %2};" : "=l"(r) : "f"(a), "f"(b));
    return r;
}
__device__ __forceinline__ void fma2(unsigned long long &acc, unsigned long long v, unsigned long long w){
    asm("fma.rn.f32x2 %0, %1, %2, %0;" : "+l"(acc) : "l"(v), "l"(w));
}
__device__ __forceinline__ void upk2(unsigned long long p, float &a, float &b){
    asm("mov.b64 {%0, %1}, %2;" : "=f"(a), "=f"(b) : "l"(p));
}
__device__ __forceinline__ unsigned int smem_u32(const void* p){
    unsigned int a;
    asm("{ .reg .u64 t; cvta.to.shared.u64 t, %1; cvt.u32.u64 %0, t; }" : "=r"(a) : "l"(p));
    return a;
}
__device__ __forceinline__ void mbar_wait(unsigned int mbar, unsigned int phase){
    asm volatile(
        "{\n\t.reg .pred P;\n"
        "LW%=:\n\t"
        "mbarrier.try_wait.parity.acquire.cta.shared::cta.b64 P, [%0], %1, 0x989680;\n\t"
        "@P bra LD%=;\n\t"
        "bra LW%=;\n"
        "LD%=:\n\t}"
        :: "r"(mbar), "r"(phase) : "memory");
}
__device__ __forceinline__ void issue_stage(unsigned int dst, const float4* src, unsigned int mbar){
    asm volatile("mbarrier.arrive.expect_tx.shared.b64 _, [%0], %1;"
                 :: "r"(mbar), "r"((unsigned)STAGE_BYTES) : "memory");
    #pragma unroll
    for (int r = 0; r < SROWS; r++){
        asm volatile("cp.async.bulk.shared::cluster.global.mbarrier::complete_tx::bytes [%0], [%1], %2, [%3];"
            :: "r"(dst + r*ROWB), "l"(src + (size_t)r*PIX4), "r"((unsigned)ROWB), "r"(mbar)
            : "memory");
    }
}

// ---------------------------------------------------------------------------
// prep: q + t accumulation (task = (h, 8-e-chunk), 1024 tasks, 2 per block).
// No barriers — the launch boundary is the sync.
// ---------------------------------------------------------------------------
__global__ void __launch_bounds__(256, 4) prep_kernel(
        const float* __restrict__ Q,
        const float* __restrict__ WQ, const float* __restrict__ bQ,
        const float* __restrict__ WK, const float* __restrict__ bK) {
    __shared__ float q_s[8];
    int tid  = threadIdx.x;
    int bx   = blockIdx.x;
    int gid  = bx*256 + tid;
    int lane = tid & 31;
    int wid  = tid >> 5;

    if (gid == 0) { g_ctr = 0; g_wready = 0; }
    if (gid < NH) g_sums[gid] = 0.f;

    const float4* Q4 = (const float4*)Q;
    #pragma unroll 1
    for (int t = bx; t < 1024; t += PGRID) {
        int h = t >> 7, e0 = (t & 127) * 8;

        // (1) WK chunk -> registers (independent of q, issued first)
        float4 wk[8];
        {
            const float4* Wp = (const float4*)(WK + (size_t)h*DD*DD + (size_t)e0*DD) + tid;
            #pragma unroll
            for (int e = 0; e < 8; e++)
                wk[e] = __ldcs(&Wp[(size_t)e*(DD/4)]);
        }

        // (2) each warp: one q_e from WQ (overlaps WK in-flight loads)
        {
            int e = e0 + wid;
            const float4* W4 = (const float4*)WQ + (size_t)h*(DD*DD/4) + (size_t)e*(DD/4);
            float acc = 0.f;
            #pragma unroll
            for (int i = 0; i < 8; i++) {
                float4 w = __ldcs(&W4[lane + i*32]);
                float4 q = Q4[lane + i*32];
                acc += w.x*q.x + w.y*q.y + w.z*q.z + w.w*q.w;
            }
            #pragma unroll
            for (int o = 16; o; o >>= 1) acc += __shfl_xor_sync(0xffffffffu, acc, o);
            if (lane == 0) q_s[wid] = acc + bQ[h*DD + e];
        }
        __syncthreads();

        // (3) c[h] partial
        if (tid < 8) {
            float v = q_s[tid] * bK[h*DD + e0 + tid];
            v += __shfl_xor_sync(0xffu, v, 4);
            v += __shfl_xor_sync(0xffu, v, 2);
            v += __shfl_xor_sync(0xffu, v, 1);
            if (tid == 0) atomicAdd(&g_c[h], v);
        }

        // (4) t[h,d] partial from register-resident wk
        float4 acc = make_float4(0.f, 0.f, 0.f, 0.f);
        #pragma unroll
        for (int e = 0; e < 8; e++) {
            float qe = q_s[e];
            acc.x = fmaf(qe, wk[e].x, acc.x);
            acc.y = fmaf(qe, wk[e].y, acc.y);
            acc.z = fmaf(qe, wk[e].z, acc.z);
            acc.w = fmaf(qe, wk[e].w, acc.w);
        }
        float* p = &g_t[h*DD + tid*4];
        asm volatile("red.global.add.v4.f32 [%0], {%1, %2, %3, %4};"
                     :: "l"(p), "f"(acc.x), "f"(acc.y), "f"(acc.z), "f"(acc.w) : "memory");
        __syncthreads();   // q_s reused next task
    }
}

// ---------------------------------------------------------------------------
// wsum + logits merged.
//  Producers (bx<256): zero d_out slice; logits/exp/sums from g_t/g_c/K;
//    threadfence; arrive g_wready.  Then join the ticket loop.
//  All blocks: ticket -> issue 4 TMA stages -> (first time: spin g_wready,
//    snapshot inv) -> w2s fill -> consume 32 stages -> REDG.v4 out.
//  Block 0 zeroes g_t/g_c after the loop (all readers provably done).
// ---------------------------------------------------------------------------
__global__ void __launch_bounds__(256, 4) wsum_kernel(const float* __restrict__ V,
                                                      const float* __restrict__ K,
                                                      float4* __restrict__ out4) {
    extern __shared__ char smem[];
    unsigned int sb = smem_u32(smem);
    int tid = threadIdx.x;
    int bx  = blockIdx.x;
    int lane = tid & 31;
    int wid  = tid >> 5;
    int grp = tid >> 7;          // head group: heads [4g, 4g+4)
    int cid = tid & 127;         // float4 column within tile

    if (tid == 0) {
        #pragma unroll
        for (int i = 0; i < STAGES; i++)
            asm volatile("mbarrier.init.shared.b64 [%0], 1;" :: "r"(sb + SM_MBAR + i*8) : "memory");
        asm volatile("fence.proxy.async.shared::cta;" ::: "memory");
    }
    __syncthreads();

    // ============ producer phase: logits (blocks 0..255) ============
    if (bx < NPROD) {
        // zero this block's d_out slice (completes before arrive)
        for (int idx = bx*256 + tid; idx < NH*PIX4; idx += NPROD*256)
            out4[idx] = make_float4(0.f, 0.f, 0.f, 0.f);

        float4* ts4 = (float4*)smem;                 // 32 KB (stage area, pre-TMA)
        float*  wsm = (float*)(smem + SM_W2S);       // 8x8 floats (w2s area)
        for (int i = tid; i < NH*DD/4; i += 256) {
            const float* s = &g_t[i*4];
            ts4[i] = make_float4(__ldcg(s), __ldcg(s+1), __ldcg(s+2), __ldcg(s+3));
        }
        __syncthreads();

        int m = bx * 8 + wid;
        const float4* K4 = (const float4*)K + (size_t)m*(DD/4);
        float acc[NH];
        #pragma unroll
        for (int h = 0; h < NH; h++) acc[h] = 0.f;
        #pragma unroll
        for (int i = 0; i < 8; i++) {
            float4 k4 = K4[lane + i*32];
            #pragma unroll
            for (int h = 0; h < NH; h++) {
                float4 t4 = ts4[h*256 + lane + i*32];
                acc[h] += k4.x*t4.x + k4.y*t4.y + k4.z*t4.z + k4.w*t4.w;
            }
        }
        #pragma unroll
        for (int h = 0; h < NH; h++) {
            #pragma unroll
            for (int o = 16; o; o >>= 1) acc[h] += __shfl_xor_sync(0xffffffffu, acc[h], o);
        }
        if (lane == 0) {
            #pragma unroll
            for (int h = 0; h < NH; h++) {
                float w = expf((acc[h] + __ldcg(&g_c[h])) * (1.0f/1024.0f));
                g_wt[m*NH + h] = w;
                wsm[wid*NH + h] = w;
            }
        }
        __syncthreads();
        if (tid < NH) {
            float s = 0.f;
            #pragma unroll
            for (int w8 = 0; w8 < 8; w8++) s += wsm[w8*NH + tid];
            atomicAdd(&g_sums[tid], s);
        }
        __threadfence();
        __syncthreads();
        if (tid == 0) atomicAdd(&g_wready, 1);
        __syncthreads();
    }

    // ============ ticket loop (all blocks) ============
    unsigned long long* w2s = (unsigned long long*)(smem + SM_W2S);
    int* s_tile = (int*)(smem + SM_TILE);
    int sc = 0;
    bool waited = false;
    float inv[NH];

    for (;;) {
        if (tid == 0) *s_tile = atomicAdd(&g_ctr, 1);
        __syncthreads();
        int t = *s_tile;
        if (t >= NTILES) break;
        int s  = t / XT;
        int xb = t - s*XT;
        int m0 = s * MSLICE;

        // TMA first — independent of weights
        const float4* src = (const float4*)V + (size_t)m0*PIX4 + xb*XTW;
        if (tid == 0) {
            #pragma unroll
            for (int j = 0; j < STAGES; j++)
                issue_stage(sb + ((sc + j) & (STAGES-1))*STAGE_BYTES,
                            src + (size_t)j*SROWS*PIX4,
                            sb + SM_MBAR + ((sc + j) & (STAGES-1))*8);
        }

        if (!waited) {       // first tile: weights must be published
            if (tid == 0) {
                while (*(volatile int*)&g_wready < NPROD) __nanosleep(64);
            }
            __syncthreads();
            __threadfence();
            #pragma unroll
            for (int h = 0; h < NH; h++) inv[h] = __fdividef(1.0f, g_sums[h]);
            waited = true;
        }

        for (int i = tid; i < MSLICE*NH; i += 256) {
            float w = g_wt[m0*NH + i] * inv[i & 7];
            w2s[i] = pk2(w, w);
        }
        __syncthreads();

        unsigned long long a0[4], a1[4];
        #pragma unroll
        for (int i = 0; i < 4; i++) { a0[i] = 0ull; a1[i] = 0ull; }

        #pragma unroll 1
        for (int j = 0; j < NSTG; j++) {
            int slot = (sc + j) & (STAGES-1);
            unsigned int ph = ((unsigned)(sc + j) >> 2) & 1;
            mbar_wait(sb + SM_MBAR + slot*8, ph);
            const float4* vstage = (const float4*)(smem + slot*STAGE_BYTES);
            #pragma unroll
            for (int r = 0; r < SROWS; r++) {
                float4 v = vstage[r*XTW + cid];
                unsigned long long v01 = pk2(v.x, v.y);
                unsigned long long v23 = pk2(v.z, v.w);
                const ulonglong2* wr = (const ulonglong2*)&w2s[(j*SROWS + r)*NH + grp*4];
                ulonglong2 wA = wr[0], wB = wr[1];
                fma2(a0[0], v01, wA.x); fma2(a1[0], v23, wA.x);
                fma2(a0[1], v01, wA.y); fma2(a1[1], v23, wA.y);
                fma2(a0[2], v01, wB.x); fma2(a1[2], v23, wB.x);
                fma2(a0[3], v01, wB.y); fma2(a1[3], v23, wB.y);
            }
            __syncthreads();
            if (tid == 0 && j + STAGES < NSTG)
                issue_stage(sb + ((sc + j + STAGES) & (STAGES-1))*STAGE_BYTES,
                            src + (size_t)(j + STAGES)*SROWS*PIX4,
                            sb + SM_MBAR + ((sc + j + STAGES) & (STAGES-1))*8);
        }
        sc += NSTG;

        int jj = xb*XTW + cid;
        #pragma unroll
        for (int i = 0; i < 4; i++) {
            int h = grp*4 + i;
            float x, y, z, w;
            upk2(a0[i], x, y);
            upk2(a1[i], z, w);
            float* p = (float*)&out4[h*PIX4 + jj];
            asm volatile("red.global.add.v4.f32 [%0], {%1, %2, %3, %4};"
                         :: "l"(p), "f"(x), "f"(y), "f"(z), "f"(w) : "memory");
        }
    }

    // block 0: zero g_t/g_c for the next replay (all g_t readers arrived long ago)
    if (bx == 0) {
        if (tid == 0) {
            while (*(volatile int*)&g_wready < NPROD) __nanosleep(64);
        }
        __syncthreads();
        float4* t4 = (float4*)g_t;
        #pragma unroll
        for (int i = 0; i < NH*DD/4/256; i++)
            t4[i*256 + tid] = make_float4(0.f, 0.f, 0.f, 0.f);
        if (tid < NH) g_c[tid] = 0.f;
    }
}

extern "C" void kernel_launch(void* const* d_in, const int* in_sizes, int n_in,
                              void* d_out, int out_size) {
    const float* Q  = (const float*)d_in[0];
    const float* K  = (const float*)d_in[1];
    const float* V  = (const float*)d_in[2];
    const float* WQ = (const float*)d_in[3];
    const float* bQ = (const float*)d_in[4];
    const float* WK = (const float*)d_in[5];
    const float* bK = (const float*)d_in[6];

    prep_kernel<<<PGRID, 256>>>(Q, WQ, bQ, WK, bK);
    wsum_kernel<<<WGRID, 256, SM_TOTAL>>>(V, K, (float4*)d_out);
}

// round 17
// speedup vs baseline: 1.1018x; 1.1008x over previous
#include <cuda_runtime.h>

#define NH 8
#define DD 1024
#define MM 2048
#define PIX4 12288           // 128*128*3 / 4
#define MSLICE 128           // m per wsum tile
#define XTW 128              // float4 columns per wsum tile
#define XT (PIX4/XTW)        // 96
#define NTILES (XT*(MM/MSLICE))   // 96*16 = 1536
#define WGRID 608            // wsum grid: 152 SMs x 4

#define STAGES 4
#define SROWS 4                          // m-rows per stage
#define ROWB (XTW*16)                    // 2048 bytes per row
#define STAGE_BYTES (SROWS*ROWB)         // 8192
#define NSTG (MSLICE/SROWS)              // 32 stages per tile
// dynamic smem layout (wsum)
#define SM_W2S   (STAGES*STAGE_BYTES)    // 32768
#define SM_MBAR  (SM_W2S + MSLICE*NH*8)  // 40960
#define SM_TILE  (SM_MBAR + STAGES*8)    // 40992
#define SM_TOTAL (SM_TILE + 16)          // 41008

// Replay lifecycle (3 launches):
//   proj_qt : resets g_ctr, zeroes g_sums; REDG-accumulates g_t, atomics g_c
//             (g_t/g_c zeroed by the PREVIOUS wsum; module load zeroes run 1)
//   logits  : reads g_t/g_c/K -> g_wt, accumulates g_sums, zeroes d_out
//   wsum    : consumes g_wt/g_sums/g_ctr; block 0 zeroes g_t/g_c for next replay
__device__ float g_t[NH*DD];
__device__ float g_c[NH];
__device__ float g_sums[NH];
__device__ float g_wt[MM*NH];
__device__ int   g_ctr;

__device__ __forceinline__ unsigned long long pk2(float a, float b){
    unsigned long long r;
    asm("mov.b64 %0, {%1, %2};" : "=l"(r) : "f"(a), "f"(b));
    return r;
}
__device__ __forceinline__ void fma2(unsigned long long &acc, unsigned long long v, unsigned long long w){
    asm("fma.rn.f32x2 %0, %1, %2, %0;" : "+l"(acc) : "l"(v), "l"(w));
}
__device__ __forceinline__ void upk2(unsigned long long p, float &a, float &b){
    asm("mov.b64 {%0, %1}, %2;" : "=f"(a), "=f"(b) : "l"(p));
}
__device__ __forceinline__ unsigned int smem_u32(const void* p){
    unsigned int a;
    asm("{ .reg .u64 t; cvta.to.shared.u64 t, %1; cvt.u32.u64 %0, t; }" : "=r"(a) : "l"(p));
    return a;
}
__device__ __forceinline__ void mbar_wait(unsigned int mbar, unsigned int phase){
    asm volatile(
        "{\n\t.reg .pred P;\n"
        "LW%=:\n\t"
        "mbarrier.try_wait.parity.acquire.cta.shared::cta.b64 P, [%0], %1, 0x989680;\n\t"
        "@P bra LD%=;\n\t"
        "bra LW%=;\n"
        "LD%=:\n\t}"
        :: "r"(mbar), "r"(phase) : "memory");
}
__device__ __forceinline__ void issue_stage(unsigned int dst, const float4* src, unsigned int mbar){
    asm volatile("mbarrier.arrive.expect_tx.shared.b64 _, [%0], %1;"
                 :: "r"(mbar), "r"((unsigned)STAGE_BYTES) : "memory");
    #pragma unroll
    for (int r = 0; r < SROWS; r++){
        asm volatile("cp.async.bulk.shared::cluster.global.mbarrier::complete_tx::bytes [%0], [%1], %2, [%3];"
            :: "r"(dst + r*ROWB), "l"(src + (size_t)r*PIX4), "r"((unsigned)ROWB), "r"(mbar)
            : "memory");
    }
}

// ---------------------------------------------------------------------------
// proj_qt: block-local fusion of q-projection and t-accumulation.
//   1024 blocks, ONE task each: (h = by, e-chunk = bx*8).
//   8 warps: q_e = Q.WQ[h,e,:] + bQ[h,e] -> smem; block sync;
//   then c[h] partial + all 256 threads: t[h,d] += sum_e q_e*WK[h,e,d] (REDG.v4)
// ---------------------------------------------------------------------------
__global__ void __launch_bounds__(256) proj_qt_kernel(
        const float* __restrict__ Q,
        const float* __restrict__ WQ, const float* __restrict__ bQ,
        const float* __restrict__ WK, const float* __restrict__ bK) {
    __shared__ float q_s[8];
    int tid  = threadIdx.x;
    int lane = tid & 31;
    int wid  = tid >> 5;
    int h  = blockIdx.y;
    int e0 = blockIdx.x * 8;
    int gid = (blockIdx.y * gridDim.x + blockIdx.x) * 256 + tid;

    if (gid == 0) g_ctr = 0;
    if (gid < NH) g_sums[gid] = 0.f;

    // q_e per warp (4KB WQ row each)
    {
        int e = e0 + wid;
        const float4* W4 = (const float4*)WQ + (size_t)h*(DD*DD/4) + (size_t)e*(DD/4);
        const float4* Q4 = (const float4*)Q;
        float acc = 0.f;
        #pragma unroll
        for (int i = 0; i < 8; i++) {
            float4 w = __ldcs(&W4[lane + i*32]);
            float4 q = Q4[lane + i*32];
            acc += w.x*q.x + w.y*q.y + w.z*q.z + w.w*q.w;
        }
        #pragma unroll
        for (int o = 16; o; o >>= 1) acc += __shfl_xor_sync(0xffffffffu, acc, o);
        if (lane == 0) q_s[wid] = acc + bQ[h*DD + e];
    }
    __syncthreads();

    // c[h] partial over this e-chunk
    if (tid < 8) {
        float v = q_s[tid] * bK[h*DD + e0 + tid];
        v += __shfl_xor_sync(0xffu, v, 4);
        v += __shfl_xor_sync(0xffu, v, 2);
        v += __shfl_xor_sync(0xffu, v, 1);
        if (tid == 0) atomicAdd(&g_c[h], v);
    }

    // t[h,d] partial: 256 threads x float4 over d, 8 e-rows of WK (32KB)
    const float4* Wp = (const float4*)(WK + (size_t)h*DD*DD + (size_t)e0*DD) + tid;
    float4 acc = make_float4(0.f, 0.f, 0.f, 0.f);
    #pragma unroll
    for (int e = 0; e < 8; e++) {
        float qe = q_s[e];
        float4 w = __ldcs(&Wp[(size_t)e*(DD/4)]);
        acc.x = fmaf(qe, w.x, acc.x);
        acc.y = fmaf(qe, w.y, acc.y);
        acc.z = fmaf(qe, w.z, acc.z);
        acc.w = fmaf(qe, w.w, acc.w);
    }
    float* p = &g_t[h*DD + tid*4];
    asm volatile("red.global.add.v4.f32 [%0], {%1, %2, %3, %4};"
                 :: "l"(p), "f"(acc.x), "f"(acc.y), "f"(acc.z), "f"(acc.w) : "memory");
}

// ---------------------------------------------------------------------------
// logits (R5-proven): fused logits + exp (unnormalized softmax) + sums.
//   g_wt[m][h] = exp((K[m].t[h] + c[h]) / 1024)   (no max-sub: |l| small)
//   Zero-inits d_out.
// ---------------------------------------------------------------------------
__global__ void logits_kernel(const float* __restrict__ K,
                              float4* __restrict__ out4) {
    __shared__ float4 ts4[NH*DD/4];   // 32 KB
    __shared__ float ws[8][NH];
    int tid = threadIdx.x;
    for (int i = tid; i < NH*DD/4; i += 256)
        ts4[i] = ((const float4*)g_t)[i];

    for (int idx = blockIdx.x * 256 + tid; idx < NH*PIX4; idx += 256*256)
        out4[idx] = make_float4(0.f, 0.f, 0.f, 0.f);
    __syncthreads();

    int wid = tid >> 5;
    int m = blockIdx.x * 8 + wid;
    int lane = tid & 31;
    const float4* K4 = (const float4*)K + (size_t)m*(DD/4);
    float acc[NH];
    #pragma unroll
    for (int h = 0; h < NH; h++) acc[h] = 0.f;
    #pragma unroll
    for (int i = 0; i < 8; i++) {
        float4 k4 = K4[lane + i*32];
        #pragma unroll
        for (int h = 0; h < NH; h++) {
            float4 t4 = ts4[h*256 + lane + i*32];
            acc[h] += k4.x*t4.x + k4.y*t4.y + k4.z*t4.z + k4.w*t4.w;
        }
    }
    #pragma unroll
    for (int h = 0; h < NH; h++) {
        #pragma unroll
        for (int o = 16; o; o >>= 1) acc[h] += __shfl_xor_sync(0xffffffffu, acc[h], o);
    }
    if (lane == 0) {
        #pragma unroll
        for (int h = 0; h < NH; h++) {
            float w = expf((acc[h] + g_c[h]) * (1.0f/1024.0f));
            g_wt[m*NH + h] = w;
            ws[wid][h] = w;
        }
    }
    __syncthreads();
    if (tid < NH) {
        float s = 0.f;
        #pragma unroll
        for (int w8 = 0; w8 < 8; w8++) s += ws[w8][tid];
        atomicAdd(&g_sums[tid], s);
    }
}

// ---------------------------------------------------------------------------
// wsum (R14-proven 70.5us, byte-identical): persistent tickets; 256KB tiles;
// cp.async.bulk 4-stage smem ring; 2 head-grps x 128 cols; f32x2 FMA; REDG.v4.
// Block 0 zeroes g_t/g_c for the next graph replay (untouched by wsum).
// ---------------------------------------------------------------------------
__global__ void __launch_bounds__(256, 4) wsum_kernel(const float* __restrict__ V,
                                                      float4* __restrict__ out4) {
    extern __shared__ char smem[];
    unsigned int sb = smem_u32(smem);
    int tid = threadIdx.x;
    int grp = tid >> 7;          // head group: heads [4g, 4g+4)
    int cid = tid & 127;         // float4 column within tile

    if (blockIdx.x == 0) {       // next-replay state reset
        if (tid < NH) g_c[tid] = 0.f;
        float4* t4 = (float4*)g_t;
        #pragma unroll
        for (int i = 0; i < NH*DD/4/256; i++)
            t4[i*256 + tid] = make_float4(0.f, 0.f, 0.f, 0.f);
    }

    if (tid == 0) {
        #pragma unroll
        for (int i = 0; i < STAGES; i++)
            asm volatile("mbarrier.init.shared.b64 [%0], 1;" :: "r"(sb + SM_MBAR + i*8) : "memory");
        asm volatile("fence.proxy.async.shared::cta;" ::: "memory");
    }
    __syncthreads();

    float inv[NH];
    #pragma unroll
    for (int h = 0; h < NH; h++) inv[h] = __fdividef(1.0f, g_sums[h]);

    unsigned long long* w2s = (unsigned long long*)(smem + SM_W2S);
    int* s_tile = (int*)(smem + SM_TILE);
    int sc = 0;   // absolute stage counter -> slot/parity

    for (;;) {
        if (tid == 0) *s_tile = atomicAdd(&g_ctr, 1);
        __syncthreads();
        int t = *s_tile;
        if (t >= NTILES) break;
        int s  = t / XT;
        int xb = t - s*XT;
        int m0 = s * MSLICE;

        const float4* src = (const float4*)V + (size_t)m0*PIX4 + xb*XTW;
        if (tid == 0) {
            #pragma unroll
            for (int j = 0; j < STAGES; j++)
                issue_stage(sb + ((sc + j) & (STAGES-1))*STAGE_BYTES,
                            src + (size_t)j*SROWS*PIX4,
                            sb + SM_MBAR + ((sc + j) & (STAGES-1))*8);
        }

        for (int i = tid; i < MSLICE*NH; i += 256) {
            float w = g_wt[m0*NH + i] * inv[i & 7];
            w2s[i] = pk2(w, w);
        }
        __syncthreads();

        unsigned long long a0[4], a1[4];
        #pragma unroll
        for (int i = 0; i < 4; i++) { a0[i] = 0ull; a1[i] = 0ull; }

        #pragma unroll 1
        for (int j = 0; j < NSTG; j++) {
            int slot = (sc + j) & (STAGES-1);
            unsigned int ph = ((unsigned)(sc + j) >> 2) & 1;
            mbar_wait(sb + SM_MBAR + slot*8, ph);
            const float4* vstage = (const float4*)(smem + slot*STAGE_BYTES);
            #pragma unroll
            for (int r = 0; r < SROWS; r++) {
                float4 v = vstage[r*XTW + cid];
                unsigned long long v01 = pk2(v.x, v.y);
                unsigned long long v23 = pk2(v.z, v.w);
                const ulonglong2* wr = (const ulonglong2*)&w2s[(j*SROWS + r)*NH + grp*4];
                ulonglong2 wA = wr[0], wB = wr[1];
                fma2(a0[0], v01, wA.x); fma2(a1[0], v23, wA.x);
                fma2(a0[1], v01, wA.y); fma2(a1[1], v23, wA.y);
                fma2(a0[2], v01, wB.x); fma2(a1[2], v23, wB.x);
                fma2(a0[3], v01, wB.y); fma2(a1[3], v23, wB.y);
            }
            __syncthreads();   // slot fully consumed -> safe to refill
            if (tid == 0 && j + STAGES < NSTG)
                issue_stage(sb + ((sc + j + STAGES) & (STAGES-1))*STAGE_BYTES,
                            src + (size_t)(j + STAGES)*SROWS*PIX4,
                            sb + SM_MBAR + ((sc + j + STAGES) & (STAGES-1))*8);
        }
        sc += NSTG;

        int jj = xb*XTW + cid;
        #pragma unroll
        for (int i = 0; i < 4; i++) {
            int h = grp*4 + i;
            float x, y, z, w;
            upk2(a0[i], x, y);
            upk2(a1[i], z, w);
            float* p = (float*)&out4[h*PIX4 + jj];
            asm volatile("red.global.add.v4.f32 [%0], {%1, %2, %3, %4};"
                         :: "l"(p), "f"(x), "f"(y), "f"(z), "f"(w) : "memory");
        }
    }
}

extern "C" void kernel_launch(void* const* d_in, const int* in_sizes, int n_in,
                              void* d_out, int out_size) {
    const float* Q  = (const float*)d_in[0];
    const float* K  = (const float*)d_in[1];
    const float* V  = (const float*)d_in[2];
    const float* WQ = (const float*)d_in[3];
    const float* bQ = (const float*)d_in[4];
    const float* WK = (const float*)d_in[5];
    const float* bK = (const float*)d_in[6];

    proj_qt_kernel<<<dim3(128, 8), 256>>>(Q, WQ, bQ, WK, bK);
    logits_kernel<<<256, 256>>>(K, (float4*)d_out);
    wsum_kernel<<<WGRID, 256, SM_TOTAL>>>(V, (float4*)d_out);
}